// round 6
// baseline (speedup 1.0000x reference)
#include <cuda_runtime.h>
#include <math.h>

#define KPAD   320        // >= Kv (297 for box=20, dl=4), multiple of 64
#define BMAX   8
#define NMAX   2048
#define NSPLIT 16
#define KITER  (KPAD/32)  // 10

// ---------------- scratch (zero-initialized device globals) ----------------
__device__ int   g_Kv[BMAX];
__device__ int4  g_kint[BMAX][KPAD];
__device__ float g_part[NSPLIT][4][BMAX][KPAD][64];
__device__ float g_kpotT[2][BMAX][64][KPAD];   // k_pot re/im, [d][k] transposed
__device__ float g_vpot[2][BMAX][KPAD][64];    // v_pot re/im, [k][d]
__device__ float g_QT[BMAX][64][NMAX];         // Q transposed [d][n]
__device__ float g_Zre[BMAX][NMAX][KPAD];
__device__ float g_Zim[BMAX][NMAX][KPAD];
__device__ float g_P[BMAX][NMAX][KPAD];        // softmax probabilities

// ---------------- K0: valid k-list, warp-parallel ordered compaction -------
// Bit-exact emulation of reference validity (no FFMA contraction; the 21
// boundary points with |k|^2 == 25 must be INCLUDED). Candidate order is
// kx-major, then ky, then kz — identical to the reference loops.
__global__ void k_build(const float* __restrict__ cell)
{
    int b = blockIdx.x;
    int lane = threadIdx.x;
    float bx = cell[b*9 + 0];
    float by = cell[b*9 + 4];
    float bz = cell[b*9 + 8];
    int nkx = max(1, (int)(bx / 4.0f));
    int nky = max(1, (int)(by / 4.0f));
    int nkz = max(1, (int)(bz / 4.0f));
    const float TWOPI_SQ = 39.47841760435743f;   // (2*pi)^2
    const float KSQMAX   = 2.4674011002723395f;  // (2*pi/4)^2
    int ny = 2*nky + 1, nz = 2*nkz + 1;
    int total = (nkx + 1) * ny * nz;
    int cnt = 0;
    for (int base = 0; base < total; base += 32) {
        int idx = base + lane;
        bool valid = false;
        int kx = 0, ky = 0, kz = 0;
        if (idx < total) {
            kx = idx / (ny * nz);
            int r = idx % (ny * nz);
            ky = r / nz - nky;
            kz = r % nz - nkz;
            float fx = __fdiv_rn((float)kx, bx);
            float fy = __fdiv_rn((float)ky, by);
            float fz = __fdiv_rn((float)kz, bz);
            float sx = __fmul_rn(fx, fx);
            float sy = __fmul_rn(fy, fy);
            float sz = __fmul_rn(fz, fz);
            float s  = __fadd_rn(__fadd_rn(sx, sy), sz);
            float ksq = __fmul_rn(TWOPI_SQ, s);
            valid = (ksq <= KSQMAX) && (ksq > 0.0f);
        }
        unsigned m = __ballot_sync(0xffffffffu, valid);
        int pos = cnt + __popc(m & ((1u << lane) - 1u));
        if (valid && pos < KPAD) g_kint[b][pos] = make_int4(kx, ky, kz, 0);
        cnt += __popc(m);
    }
    if (lane == 0) g_Kv[b] = min(cnt, KPAD);
}

// ---------------- K0b: transpose Q into [d][n] ------------------------------
__global__ void k_qT(const float* __restrict__ qmat, int n)
{
    __shared__ float tile[32][33];
    int b  = blockIdx.z;
    int n0 = blockIdx.x * 32;
    int d0 = blockIdx.y * 32;
    int x = threadIdx.x, y = threadIdx.y;
    #pragma unroll
    for (int i = 0; i < 32; i += 8)
        tile[y + i][x] = qmat[((size_t)(b*n + n0 + y + i)) * 64 + d0 + x];
    __syncthreads();
    #pragma unroll
    for (int i = 0; i < 32; i += 8)
        g_QT[b][d0 + y + i][n0 + x] = tile[x][y + i];
}

// compose e^{i 2pi k.u} from per-axis phasor tables (tc/ts indexed [axis][m])
__device__ __forceinline__ void compose_e(const float* tc, const float* ts,
                                          int4 kv, float& c, float& s)
{
    float cx = tc[0*6 + kv.x];
    float sx = ts[0*6 + kv.x];
    int ay = abs(kv.y);
    float cy = tc[1*6 + ay];
    float sy = ts[1*6 + ay];
    sy = (kv.y < 0) ? -sy : sy;
    int az = abs(kv.z);
    float cz = tc[2*6 + az];
    float sz = ts[2*6 + az];
    sz = (kv.z < 0) ? -sz : sz;
    float c1 = cx*cy - sx*sy;
    float s1 = cx*sy + sx*cy;
    c = c1*cz - s1*sz;
    s = c1*sz + s1*cz;
}

// ---------------- K2: k_pot/v_pot partials — 64k x 64d CTA tile ------------
__global__ void __launch_bounds__(256) k_pot(const float* __restrict__ kmat,
                                             const float* __restrict__ vmat,
                                             const float* __restrict__ pos,
                                             const float* __restrict__ cell,
                                             int n)
{
    int b  = blockIdx.z;
    int Kv = g_Kv[b];
    int k0 = blockIdx.x * 64;
    int nper = n / NSPLIT;          // 128
    int n0 = blockIdx.y * nper;
    int t  = threadIdx.x;
    int tk = t >> 4;                // k group 0..15
    int td = t & 15;                // d group 0..15

    __shared__ float tabc[128][3][6], tabs[128][3][6];
    __shared__ float sEc[16][64], sEs[16][64];
    __shared__ float sK[16][64], sV[16][64];
    __shared__ int4  skint[64];

    float invb[3] = { 1.0f / cell[b*9 + 0], 1.0f / cell[b*9 + 4], 1.0f / cell[b*9 + 8] };

    for (int fid = t; fid < 128 * 18; fid += 256) {
        int node = fid / 18; int rem = fid % 18; int a = rem / 6; int m = rem % 6;
        float u = pos[((size_t)(b*n + n0 + node)) * 3 + a] * invb[a];
        float tt = u * (float)m;
        tt -= floorf(tt);
        float sv, cv; sincospif(2.0f * tt, &sv, &cv);
        tabc[node][a][m] = cv;
        tabs[node][a][m] = sv;
    }
    if (t < 64) skint[t] = g_kint[b][k0 + t];

    float akr[4][4] = {}, aki[4][4] = {}, avr[4][4] = {}, avi[4][4] = {};
    __syncthreads();

    for (int nc = 0; nc < nper; nc += 16) {
        {
            int node = t >> 4, dq = t & 15;
            const float4* kp = (const float4*)(kmat + (size_t)(b*n + n0 + nc + node) * 64);
            const float4* vp = (const float4*)(vmat + (size_t)(b*n + n0 + nc + node) * 64);
            *(float4*)&sK[node][dq*4] = kp[dq];
            *(float4*)&sV[node][dq*4] = vp[dq];
        }
        #pragma unroll
        for (int r = 0; r < 4; r++) {
            int fid = t + r * 256;
            int nn = fid >> 6, kx = fid & 63;
            float c, s;
            compose_e(&tabc[nc + nn][0][0], &tabs[nc + nn][0][0], skint[kx], c, s);
            sEc[nn][kx] = c;
            sEs[nn][kx] = s;
        }
        __syncthreads();
        #pragma unroll
        for (int nn = 0; nn < 16; nn++) {
            float4 ec4 = *(const float4*)&sEc[nn][tk*4];
            float4 es4 = *(const float4*)&sEs[nn][tk*4];
            float4 xk4 = *(const float4*)&sK[nn][td*4];
            float4 xv4 = *(const float4*)&sV[nn][td*4];
            float ec[4] = {ec4.x, ec4.y, ec4.z, ec4.w};
            float es[4] = {es4.x, es4.y, es4.z, es4.w};
            float xk[4] = {xk4.x, xk4.y, xk4.z, xk4.w};
            float xv[4] = {xv4.x, xv4.y, xv4.z, xv4.w};
            #pragma unroll
            for (int i = 0; i < 4; i++)
                #pragma unroll
                for (int j = 0; j < 4; j++) {
                    akr[i][j] += ec[i] * xk[j];
                    aki[i][j] += es[i] * xk[j];
                    avr[i][j] += ec[i] * xv[j];
                    avi[i][j] += es[i] * xv[j];
                }
        }
        __syncthreads();
    }

    int s = blockIdx.y;
    #pragma unroll
    for (int i = 0; i < 4; i++) {
        int kk = k0 + tk*4 + i;
        if (kk < Kv) {
            *(float4*)&g_part[s][0][b][kk][td*4] = make_float4(akr[i][0], akr[i][1], akr[i][2], akr[i][3]);
            *(float4*)&g_part[s][1][b][kk][td*4] = make_float4(aki[i][0], aki[i][1], aki[i][2], aki[i][3]);
            *(float4*)&g_part[s][2][b][kk][td*4] = make_float4(avr[i][0], avr[i][1], avr[i][2], avr[i][3]);
            *(float4*)&g_part[s][3][b][kk][td*4] = make_float4(avi[i][0], avi[i][1], avi[i][2], avi[i][3]);
        }
    }
}

// ---------------- K2b: deterministic split reduction -----------------------
__global__ void k_reduce(int B)
{
    int idx = blockIdx.x * 256 + threadIdx.x;
    int total = 4 * B * KPAD * 64;
    if (idx >= total) return;
    int d  = idx & 63;
    int k  = (idx >> 6) % KPAD;
    int rb = (idx >> 6) / KPAD;
    int b  = rb % B;
    int m  = rb / B;
    if (k >= g_Kv[b]) return;
    float s = 0.f;
    #pragma unroll
    for (int sp = 0; sp < NSPLIT; sp++) s += g_part[sp][m][b][k][d];
    if (m < 2) g_kpotT[m][b][d][k] = s;
    else       g_vpot[m - 2][b][k][d] = s;
}

// ---------------- K3: Z = Q @ kpot^T — 64n x 64k CTA, 8n x 4k threads ------
__global__ void __launch_bounds__(128) k_z(int n)
{
    int b  = blockIdx.z;
    int k0 = blockIdx.x * 64;
    int n0 = blockIdx.y * 64;
    int t  = threadIdx.x;
    int tk = t & 15;                // 16 groups x 4k
    int tn = t >> 4;                // 8 groups x 8n

    __shared__ float sQT[64][64];   // [d][node]
    __shared__ float sKR[64][64];   // [d][k]
    __shared__ float sKI[64][64];   // [d][k]

    #pragma unroll
    for (int r = 0; r < 8; r++) {
        int fid = t + r * 128;
        int d = fid >> 4, nq = fid & 15;
        *(float4*)&sQT[d][nq*4] = *(const float4*)&g_QT[b][d][n0 + nq*4];
    }
    #pragma unroll
    for (int r = 0; r < 8; r++) {
        int fid = t + r * 128;
        int d = fid >> 4, kq = fid & 15;
        *(float4*)&sKR[d][kq*4] = *(const float4*)&g_kpotT[0][b][d][k0 + kq*4];
        *(float4*)&sKI[d][kq*4] = *(const float4*)&g_kpotT[1][b][d][k0 + kq*4];
    }

    float zr[8][4] = {}, zi[8][4] = {};
    __syncthreads();

    #pragma unroll 4
    for (int dd = 0; dd < 64; dd++) {
        float4 a0 = *(const float4*)&sQT[dd][tn*8];
        float4 a1 = *(const float4*)&sQT[dd][tn*8 + 4];
        float4 br = *(const float4*)&sKR[dd][tk*4];
        float4 bi = *(const float4*)&sKI[dd][tk*4];
        float aa[8] = {a0.x, a0.y, a0.z, a0.w, a1.x, a1.y, a1.z, a1.w};
        float brr[4] = {br.x, br.y, br.z, br.w};
        float bii[4] = {bi.x, bi.y, bi.z, bi.w};
        #pragma unroll
        for (int i = 0; i < 8; i++)
            #pragma unroll
            for (int j = 0; j < 4; j++) {
                zr[i][j] += aa[i] * brr[j];
                zi[i][j] += aa[i] * bii[j];
            }
    }

    #pragma unroll
    for (int i = 0; i < 8; i++) {
        int node = n0 + tn*8 + i;
        *(float4*)&g_Zre[b][node][k0 + tk*4] = make_float4(zr[i][0], zr[i][1], zr[i][2], zr[i][3]);
        *(float4*)&g_Zim[b][node][k0 + tk*4] = make_float4(zi[i][0], zi[i][1], zi[i][2], zi[i][3]);
    }
}

// ---------------- K4: per-node softmax with inline phases; writes P --------
__global__ void __launch_bounds__(256) k_soft(const float* __restrict__ pos,
                                              const float* __restrict__ cell,
                                              int n)
{
    int b    = blockIdx.y;
    int warp = threadIdx.x >> 5;
    int lane = threadIdx.x & 31;
    int node = blockIdx.x * 8 + warp;
    if (node >= n) return;
    int Kv = g_Kv[b];

    __shared__ float tc[8][3][6];
    __shared__ float ts[8][3][6];

    if (lane < 18) {
        int a = lane / 6, m = lane % 6;
        float box = cell[b*9 + a*4];
        float u = pos[((size_t)(b*n + node)) * 3 + a] / box;
        float t = u * (float)m;
        t -= floorf(t);
        float sv, cv;
        sincospif(2.0f * t, &sv, &cv);
        tc[warp][a][m] = cv;
        ts[warp][a][m] = sv;
    }
    __syncwarp();

    float lg[KITER];
    float mx = -1e30f;
    #pragma unroll
    for (int i = 0; i < KITER; i++) {
        int k = lane + i * 32;
        if (k < Kv) {
            float ec, es;
            compose_e(&tc[warp][0][0], &ts[warp][0][0], g_kint[b][k], ec, es);
            float zrv = g_Zre[b][node][k];
            float ziv = g_Zim[b][node][k];
            lg[i] = ec * zrv - es * ziv;
            mx = fmaxf(mx, lg[i]);
        } else {
            lg[i] = -1e30f;
        }
    }
    #pragma unroll
    for (int o = 16; o > 0; o >>= 1) mx = fmaxf(mx, __shfl_xor_sync(0xffffffffu, mx, o));
    float sum = 0.f;
    #pragma unroll
    for (int i = 0; i < KITER; i++) {
        int k = lane + i * 32;
        if (k < Kv) {
            float p = __expf(lg[i] - mx);
            lg[i] = p;
            sum += p;
        }
    }
    #pragma unroll
    for (int o = 16; o > 0; o >>= 1) sum += __shfl_xor_sync(0xffffffffu, sum, o);
    float inv = 1.0f / sum;
    #pragma unroll
    for (int i = 0; i < KITER; i++) {
        int k = lane + i * 32;
        if (k < Kv) g_P[b][node][k] = lg[i] * inv;
    }
}

// ---------------- K5: OUT — 64n x 64d CTA, 8n x 4d threads -----------------
// k >= Kv contributes zero naturally (P and vpot are zero there).
__global__ void __launch_bounds__(128) k_out(const float* __restrict__ pos,
                                             const float* __restrict__ cell,
                                             float* __restrict__ out, int n)
{
    int b  = blockIdx.y;
    int n0 = blockIdx.x * 64;
    int t  = threadIdx.x;
    int td = t & 15;                // 16 groups x 4d
    int tn = t >> 4;                // 8 groups x 8n

    __shared__ float tabc[64][3][6], tabs[64][3][6];
    __shared__ float sWr[16][68], sWi[16][68];    // [kk][node] (+pad, 16B-aligned rows)
    __shared__ float sVr[16][64], sVi[16][64];    // [kk][d]
    __shared__ int4  skint[KPAD];

    float invb[3] = { 1.0f / cell[b*9 + 0], 1.0f / cell[b*9 + 4], 1.0f / cell[b*9 + 8] };

    for (int fid = t; fid < 64 * 18; fid += 128) {
        int node = fid / 18; int rem = fid % 18; int a = rem / 6; int m = rem % 6;
        float u = pos[((size_t)(b*n + n0 + node)) * 3 + a] * invb[a];
        float tt = u * (float)m;
        tt -= floorf(tt);
        float sv, cv; sincospif(2.0f * tt, &sv, &cv);
        tabc[node][a][m] = cv;
        tabs[node][a][m] = sv;
    }
    for (int i = t; i < KPAD; i += 128) skint[i] = g_kint[b][i];

    float acc[8][4] = {};
    __syncthreads();

    for (int k0c = 0; k0c < KPAD; k0c += 16) {
        // W tile: 16 kk x 64 nodes (compose e, multiply by P)
        #pragma unroll
        for (int r = 0; r < 8; r++) {
            int fid = t + r * 128;
            int kk = fid & 15, node = fid >> 4;
            float p = g_P[b][n0 + node][k0c + kk];
            float c, s;
            compose_e(&tabc[node][0][0], &tabs[node][0][0], skint[k0c + kk], c, s);
            sWr[kk][node] = p * c;
            sWi[kk][node] = p * s;
        }
        // V tile: 16 kk x 64 d (natural layout)
        #pragma unroll
        for (int r = 0; r < 2; r++) {
            int fid = t + r * 128;
            int kk = fid >> 4, dq = fid & 15;
            *(float4*)&sVr[kk][dq*4] = *(const float4*)&g_vpot[0][b][k0c + kk][dq*4];
            *(float4*)&sVi[kk][dq*4] = *(const float4*)&g_vpot[1][b][k0c + kk][dq*4];
        }
        __syncthreads();
        #pragma unroll 4
        for (int kk = 0; kk < 16; kk++) {
            float4 wra = *(const float4*)&sWr[kk][tn*8];
            float4 wrb = *(const float4*)&sWr[kk][tn*8 + 4];
            float4 wia = *(const float4*)&sWi[kk][tn*8];
            float4 wib = *(const float4*)&sWi[kk][tn*8 + 4];
            float4 vr4 = *(const float4*)&sVr[kk][td*4];
            float4 vi4 = *(const float4*)&sVi[kk][td*4];
            float wr[8] = {wra.x, wra.y, wra.z, wra.w, wrb.x, wrb.y, wrb.z, wrb.w};
            float wi[8] = {wia.x, wia.y, wia.z, wia.w, wib.x, wib.y, wib.z, wib.w};
            float vr[4] = {vr4.x, vr4.y, vr4.z, vr4.w};
            float vi[4] = {vi4.x, vi4.y, vi4.z, vi4.w};
            #pragma unroll
            for (int i = 0; i < 8; i++)
                #pragma unroll
                for (int j = 0; j < 4; j++) {
                    acc[i][j] += wr[i] * vr[j];
                    acc[i][j] -= wi[i] * vi[j];
                }
        }
        __syncthreads();
    }

    #pragma unroll
    for (int i = 0; i < 8; i++) {
        float* op = out + ((size_t)(b*n + n0 + tn*8 + i)) * 64 + td*4;
        *(float4*)op = make_float4(acc[i][0], acc[i][1], acc[i][2], acc[i][3]);
    }
}

// ---------------- launch -----------------------------------------------------
extern "C" void kernel_launch(void* const* d_in, const int* in_sizes, int n_in,
                              void* d_out, int out_size)
{
    const float* q    = (const float*)d_in[0];
    const float* kmat = (const float*)d_in[1];
    const float* vmat = (const float*)d_in[2];
    const float* pos  = (const float*)d_in[3];
    const float* cell = (const float*)d_in[4];
    // d_in[5] = batch indices (contiguous equal-size graphs; unused)

    int N = in_sizes[0] / 64;
    int B = in_sizes[4] / 9;
    int n = N / B;

    k_build<<<B, 32>>>(cell);
    k_qT<<<dim3(n / 32, 2, B), dim3(32, 8)>>>(q, n);
    k_pot<<<dim3(KPAD / 64, NSPLIT, B), 256>>>(kmat, vmat, pos, cell, n);
    int total = 4 * B * KPAD * 64;
    k_reduce<<<(total + 255) / 256, 256>>>(B);
    k_z<<<dim3(KPAD / 64, n / 64, B), 128>>>(n);
    k_soft<<<dim3(n / 8, B), 256>>>(pos, cell, n);
    k_out<<<dim3(n / 64, B), 128>>>(pos, cell, (float*)d_out, n);
}

// round 7
// speedup vs baseline: 1.0123x; 1.0123x over previous
#include <cuda_runtime.h>
#include <math.h>

#define KPAD   320        // >= Kv (297 for box=20, dl=4), multiple of 64
#define BMAX   8
#define NMAX   2048
#define NSPLIT 16
#define KITER  (KPAD/32)  // 10

// ---------------- scratch (zero-initialized device globals) ----------------
__device__ int   g_Kv[BMAX];
__device__ int4  g_kint[BMAX][KPAD];
__device__ float g_part[NSPLIT][4][BMAX][KPAD][64];
__device__ float g_kpotT[2][BMAX][64][KPAD];   // k_pot re/im, [d][k] transposed
__device__ float g_vpot[2][BMAX][KPAD][64];    // v_pot re/im, [k][d]
__device__ float g_QT[BMAX][64][NMAX];         // Q transposed [d][n]
__device__ float g_Zre[BMAX][NMAX][KPAD];
__device__ float g_Zim[BMAX][NMAX][KPAD];
__device__ float g_P[BMAX][NMAX][KPAD];        // softmax probabilities

// ---------------- packed f32x2 helpers (Blackwell FFMA2) --------------------
__device__ __forceinline__ unsigned long long pk2(float lo, float hi) {
    unsigned long long r;
    asm("mov.b64 %0, {%1, %2};" : "=l"(r) : "f"(lo), "f"(hi));
    return r;
}
__device__ __forceinline__ void fma2(unsigned long long& d,
                                     unsigned long long a, unsigned long long b) {
    asm("fma.rn.f32x2 %0, %1, %2, %0;" : "+l"(d) : "l"(a), "l"(b));
}
__device__ __forceinline__ float2 up2(unsigned long long v) {
    float2 f;
    asm("mov.b64 {%0, %1}, %2;" : "=f"(f.x), "=f"(f.y) : "l"(v));
    return f;
}

// ---------------- K0: valid k-list, warp-parallel ordered compaction -------
// Bit-exact emulation of reference validity (no FFMA contraction; the 21
// boundary points with |k|^2 == 25 must be INCLUDED).
__global__ void k_build(const float* __restrict__ cell)
{
    int b = blockIdx.x;
    int lane = threadIdx.x;
    float bx = cell[b*9 + 0];
    float by = cell[b*9 + 4];
    float bz = cell[b*9 + 8];
    int nkx = max(1, (int)(bx / 4.0f));
    int nky = max(1, (int)(by / 4.0f));
    int nkz = max(1, (int)(bz / 4.0f));
    const float TWOPI_SQ = 39.47841760435743f;   // (2*pi)^2
    const float KSQMAX   = 2.4674011002723395f;  // (2*pi/4)^2
    int ny = 2*nky + 1, nz = 2*nkz + 1;
    int total = (nkx + 1) * ny * nz;
    int cnt = 0;
    for (int base = 0; base < total; base += 32) {
        int idx = base + lane;
        bool valid = false;
        int kx = 0, ky = 0, kz = 0;
        if (idx < total) {
            kx = idx / (ny * nz);
            int r = idx % (ny * nz);
            ky = r / nz - nky;
            kz = r % nz - nkz;
            float fx = __fdiv_rn((float)kx, bx);
            float fy = __fdiv_rn((float)ky, by);
            float fz = __fdiv_rn((float)kz, bz);
            float sx = __fmul_rn(fx, fx);
            float sy = __fmul_rn(fy, fy);
            float sz = __fmul_rn(fz, fz);
            float s  = __fadd_rn(__fadd_rn(sx, sy), sz);
            float ksq = __fmul_rn(TWOPI_SQ, s);
            valid = (ksq <= KSQMAX) && (ksq > 0.0f);
        }
        unsigned m = __ballot_sync(0xffffffffu, valid);
        int pos = cnt + __popc(m & ((1u << lane) - 1u));
        if (valid && pos < KPAD) g_kint[b][pos] = make_int4(kx, ky, kz, 0);
        cnt += __popc(m);
    }
    if (lane == 0) g_Kv[b] = min(cnt, KPAD);
}

// ---------------- K0b: transpose Q into [d][n] (half of d per launch) ------
__global__ void k_qT(const float* __restrict__ qmat, int n, int d0)
{
    __shared__ float tile[32][33];
    int b  = blockIdx.z;
    int n0 = blockIdx.x * 32;
    int x = threadIdx.x, y = threadIdx.y;
    #pragma unroll
    for (int i = 0; i < 32; i += 8)
        tile[y + i][x] = qmat[((size_t)(b*n + n0 + y + i)) * 64 + d0 + x];
    __syncthreads();
    #pragma unroll
    for (int i = 0; i < 32; i += 8)
        g_QT[b][d0 + y + i][n0 + x] = tile[x][y + i];
}

// compose e^{i 2pi k.u} from per-axis phasor tables (tc/ts indexed [axis][m])
__device__ __forceinline__ void compose_e(const float* tc, const float* ts,
                                          int4 kv, float& c, float& s)
{
    float cx = tc[0*6 + kv.x];
    float sx = ts[0*6 + kv.x];
    int ay = abs(kv.y);
    float cy = tc[1*6 + ay];
    float sy = ts[1*6 + ay];
    sy = (kv.y < 0) ? -sy : sy;
    int az = abs(kv.z);
    float cz = tc[2*6 + az];
    float sz = ts[2*6 + az];
    sz = (kv.z < 0) ? -sz : sz;
    float c1 = cx*cy - sx*sy;
    float s1 = cx*sy + sx*cy;
    c = c1*cz - s1*sz;
    s = c1*sz + s1*cz;
}

// ---------------- K2: k_pot/v_pot partials — 64k x 64d CTA tile ------------
// acc pairs along k (from LDS.128 E fragments), broadcast along d.
__global__ void __launch_bounds__(256) k_pot(const float* __restrict__ kmat,
                                             const float* __restrict__ vmat,
                                             const float* __restrict__ pos,
                                             const float* __restrict__ cell,
                                             int n)
{
    int b  = blockIdx.z;
    int Kv = g_Kv[b];
    int k0 = blockIdx.x * 64;
    int nper = n / NSPLIT;          // 128
    int n0 = blockIdx.y * nper;
    int t  = threadIdx.x;
    int tk = t >> 4;                // k group 0..15
    int td = t & 15;                // d group 0..15

    __shared__ float tabc[128][3][6], tabs[128][3][6];
    __shared__ float sEc[16][64], sEs[16][64];
    __shared__ float sK[16][64], sV[16][64];
    __shared__ int4  skint[64];

    float invb[3] = { 1.0f / cell[b*9 + 0], 1.0f / cell[b*9 + 4], 1.0f / cell[b*9 + 8] };

    for (int fid = t; fid < 128 * 18; fid += 256) {
        int node = fid / 18; int rem = fid % 18; int a = rem / 6; int m = rem % 6;
        float u = pos[((size_t)(b*n + n0 + node)) * 3 + a] * invb[a];
        float tt = u * (float)m;
        tt -= floorf(tt);
        float sv, cv; sincospif(2.0f * tt, &sv, &cv);
        tabc[node][a][m] = cv;
        tabs[node][a][m] = sv;
    }
    if (t < 64) skint[t] = g_kint[b][k0 + t];

    // accumulators: [k-pair p][d j], pairs = (k 2p, k 2p+1) within tk*4 tile
    unsigned long long akr[2][4] = {}, aki[2][4] = {}, avr[2][4] = {}, avi[2][4] = {};
    __syncthreads();

    for (int nc = 0; nc < nper; nc += 16) {
        {
            int node = t >> 4, dq = t & 15;
            const float4* kp = (const float4*)(kmat + (size_t)(b*n + n0 + nc + node) * 64);
            const float4* vp = (const float4*)(vmat + (size_t)(b*n + n0 + nc + node) * 64);
            *(float4*)&sK[node][dq*4] = kp[dq];
            *(float4*)&sV[node][dq*4] = vp[dq];
        }
        #pragma unroll
        for (int r = 0; r < 4; r++) {
            int fid = t + r * 256;
            int nn = fid >> 6, kx = fid & 63;
            float c, s;
            compose_e(&tabc[nc + nn][0][0], &tabs[nc + nn][0][0], skint[kx], c, s);
            sEc[nn][kx] = c;
            sEs[nn][kx] = s;
        }
        __syncthreads();
        #pragma unroll
        for (int nn = 0; nn < 16; nn++) {
            float4 ec4 = *(const float4*)&sEc[nn][tk*4];
            float4 es4 = *(const float4*)&sEs[nn][tk*4];
            float4 xk4 = *(const float4*)&sK[nn][td*4];
            float4 xv4 = *(const float4*)&sV[nn][td*4];
            unsigned long long ecp[2] = { pk2(ec4.x, ec4.y), pk2(ec4.z, ec4.w) };
            unsigned long long esp[2] = { pk2(es4.x, es4.y), pk2(es4.z, es4.w) };
            float xk[4] = {xk4.x, xk4.y, xk4.z, xk4.w};
            float xv[4] = {xv4.x, xv4.y, xv4.z, xv4.w};
            #pragma unroll
            for (int j = 0; j < 4; j++) {
                unsigned long long bk = pk2(xk[j], xk[j]);
                unsigned long long bv = pk2(xv[j], xv[j]);
                #pragma unroll
                for (int p = 0; p < 2; p++) {
                    fma2(akr[p][j], ecp[p], bk);
                    fma2(aki[p][j], esp[p], bk);
                    fma2(avr[p][j], ecp[p], bv);
                    fma2(avi[p][j], esp[p], bv);
                }
            }
        }
        __syncthreads();
    }

    int s = blockIdx.y;
    #pragma unroll
    for (int p = 0; p < 2; p++) {
        float2 r0 = up2(akr[p][0]), r1 = up2(akr[p][1]), r2 = up2(akr[p][2]), r3 = up2(akr[p][3]);
        float2 i0 = up2(aki[p][0]), i1 = up2(aki[p][1]), i2 = up2(aki[p][2]), i3 = up2(aki[p][3]);
        float2 v0 = up2(avr[p][0]), v1 = up2(avr[p][1]), v2 = up2(avr[p][2]), v3 = up2(avr[p][3]);
        float2 w0 = up2(avi[p][0]), w1 = up2(avi[p][1]), w2 = up2(avi[p][2]), w3 = up2(avi[p][3]);
        int kkA = k0 + tk*4 + p*2;
        int kkB = kkA + 1;
        if (kkA < Kv) {
            *(float4*)&g_part[s][0][b][kkA][td*4] = make_float4(r0.x, r1.x, r2.x, r3.x);
            *(float4*)&g_part[s][1][b][kkA][td*4] = make_float4(i0.x, i1.x, i2.x, i3.x);
            *(float4*)&g_part[s][2][b][kkA][td*4] = make_float4(v0.x, v1.x, v2.x, v3.x);
            *(float4*)&g_part[s][3][b][kkA][td*4] = make_float4(w0.x, w1.x, w2.x, w3.x);
        }
        if (kkB < Kv) {
            *(float4*)&g_part[s][0][b][kkB][td*4] = make_float4(r0.y, r1.y, r2.y, r3.y);
            *(float4*)&g_part[s][1][b][kkB][td*4] = make_float4(i0.y, i1.y, i2.y, i3.y);
            *(float4*)&g_part[s][2][b][kkB][td*4] = make_float4(v0.y, v1.y, v2.y, v3.y);
            *(float4*)&g_part[s][3][b][kkB][td*4] = make_float4(w0.y, w1.y, w2.y, w3.y);
        }
    }
}

// ---------------- K2b: deterministic split reduction -----------------------
__global__ void k_reduce(int B)
{
    int idx = blockIdx.x * 256 + threadIdx.x;
    int total = 4 * B * KPAD * 64;
    if (idx >= total) return;
    int d  = idx & 63;
    int k  = (idx >> 6) % KPAD;
    int rb = (idx >> 6) / KPAD;
    int b  = rb % B;
    int m  = rb / B;
    if (k >= g_Kv[b]) return;
    float s = 0.f;
    #pragma unroll
    for (int sp = 0; sp < NSPLIT; sp++) s += g_part[sp][m][b][k][d];
    if (m < 2) g_kpotT[m][b][d][k] = s;
    else       g_vpot[m - 2][b][k][d] = s;
}

// ---------------- K3: Z = Q @ kpot^T — 64n x 64k CTA, 8n x 4k threads ------
// acc pairs along n (from LDS.128 Q fragments), broadcast along k.
__global__ void __launch_bounds__(128) k_z(int n)
{
    int b  = blockIdx.z;
    int k0 = blockIdx.x * 64;
    int n0 = blockIdx.y * 64;
    int t  = threadIdx.x;
    int tk = t & 15;                // 16 groups x 4k
    int tn = t >> 4;                // 8 groups x 8n

    __shared__ float sQT[64][64];   // [d][node]
    __shared__ float sKR[64][64];   // [d][k]
    __shared__ float sKI[64][64];   // [d][k]

    #pragma unroll
    for (int r = 0; r < 8; r++) {
        int fid = t + r * 128;
        int d = fid >> 4, nq = fid & 15;
        *(float4*)&sQT[d][nq*4] = *(const float4*)&g_QT[b][d][n0 + nq*4];
    }
    #pragma unroll
    for (int r = 0; r < 8; r++) {
        int fid = t + r * 128;
        int d = fid >> 4, kq = fid & 15;
        *(float4*)&sKR[d][kq*4] = *(const float4*)&g_kpotT[0][b][d][k0 + kq*4];
        *(float4*)&sKI[d][kq*4] = *(const float4*)&g_kpotT[1][b][d][k0 + kq*4];
    }

    unsigned long long zr2[4][4] = {}, zi2[4][4] = {};  // [n-pair][k j]
    __syncthreads();

    #pragma unroll 4
    for (int dd = 0; dd < 64; dd++) {
        float4 a0 = *(const float4*)&sQT[dd][tn*8];
        float4 a1 = *(const float4*)&sQT[dd][tn*8 + 4];
        float4 br = *(const float4*)&sKR[dd][tk*4];
        float4 bi = *(const float4*)&sKI[dd][tk*4];
        unsigned long long ap[4] = { pk2(a0.x, a0.y), pk2(a0.z, a0.w),
                                     pk2(a1.x, a1.y), pk2(a1.z, a1.w) };
        float brr[4] = {br.x, br.y, br.z, br.w};
        float bii[4] = {bi.x, bi.y, bi.z, bi.w};
        #pragma unroll
        for (int j = 0; j < 4; j++) {
            unsigned long long bb = pk2(brr[j], brr[j]);
            unsigned long long cc = pk2(bii[j], bii[j]);
            #pragma unroll
            for (int p = 0; p < 4; p++) {
                fma2(zr2[p][j], ap[p], bb);
                fma2(zi2[p][j], ap[p], cc);
            }
        }
    }

    #pragma unroll
    for (int p = 0; p < 4; p++) {
        float2 r0 = up2(zr2[p][0]), r1 = up2(zr2[p][1]), r2 = up2(zr2[p][2]), r3 = up2(zr2[p][3]);
        float2 i0 = up2(zi2[p][0]), i1 = up2(zi2[p][1]), i2 = up2(zi2[p][2]), i3 = up2(zi2[p][3]);
        int nodeA = n0 + tn*8 + p*2;
        int nodeB = nodeA + 1;
        *(float4*)&g_Zre[b][nodeA][k0 + tk*4] = make_float4(r0.x, r1.x, r2.x, r3.x);
        *(float4*)&g_Zim[b][nodeA][k0 + tk*4] = make_float4(i0.x, i1.x, i2.x, i3.x);
        *(float4*)&g_Zre[b][nodeB][k0 + tk*4] = make_float4(r0.y, r1.y, r2.y, r3.y);
        *(float4*)&g_Zim[b][nodeB][k0 + tk*4] = make_float4(i0.y, i1.y, i2.y, i3.y);
    }
}

// ---------------- K4: per-node softmax with inline phases; writes P --------
__global__ void __launch_bounds__(256) k_soft(const float* __restrict__ pos,
                                              const float* __restrict__ cell,
                                              int n)
{
    int b    = blockIdx.y;
    int warp = threadIdx.x >> 5;
    int lane = threadIdx.x & 31;
    int node = blockIdx.x * 8 + warp;
    if (node >= n) return;
    int Kv = g_Kv[b];

    __shared__ float tc[8][3][6];
    __shared__ float ts[8][3][6];

    if (lane < 18) {
        int a = lane / 6, m = lane % 6;
        float box = cell[b*9 + a*4];
        float u = pos[((size_t)(b*n + node)) * 3 + a] / box;
        float t = u * (float)m;
        t -= floorf(t);
        float sv, cv;
        sincospif(2.0f * t, &sv, &cv);
        tc[warp][a][m] = cv;
        ts[warp][a][m] = sv;
    }
    __syncwarp();

    float lg[KITER];
    float mx = -1e30f;
    #pragma unroll
    for (int i = 0; i < KITER; i++) {
        int k = lane + i * 32;
        if (k < Kv) {
            float ec, es;
            compose_e(&tc[warp][0][0], &ts[warp][0][0], g_kint[b][k], ec, es);
            float zrv = g_Zre[b][node][k];
            float ziv = g_Zim[b][node][k];
            lg[i] = ec * zrv - es * ziv;
            mx = fmaxf(mx, lg[i]);
        } else {
            lg[i] = -1e30f;
        }
    }
    #pragma unroll
    for (int o = 16; o > 0; o >>= 1) mx = fmaxf(mx, __shfl_xor_sync(0xffffffffu, mx, o));
    float sum = 0.f;
    #pragma unroll
    for (int i = 0; i < KITER; i++) {
        int k = lane + i * 32;
        if (k < Kv) {
            float p = __expf(lg[i] - mx);
            lg[i] = p;
            sum += p;
        }
    }
    #pragma unroll
    for (int o = 16; o > 0; o >>= 1) sum += __shfl_xor_sync(0xffffffffu, sum, o);
    float inv = 1.0f / sum;
    #pragma unroll
    for (int i = 0; i < KITER; i++) {
        int k = lane + i * 32;
        if (k < Kv) g_P[b][node][k] = lg[i] * inv;
    }
}

// ---------------- K5: OUT — 64n x 64d CTA, 8n x 4d threads -----------------
// acc pairs along n (from LDS.128 W fragments), broadcast along d.
// sVi stored negated so the im-part accumulates via fma (exact).
__global__ void __launch_bounds__(128) k_out(const float* __restrict__ pos,
                                             const float* __restrict__ cell,
                                             float* __restrict__ out, int n)
{
    int b  = blockIdx.y;
    int n0 = blockIdx.x * 64;
    int t  = threadIdx.x;
    int td = t & 15;                // 16 groups x 4d
    int tn = t >> 4;                // 8 groups x 8n

    __shared__ float tabc[64][3][6], tabs[64][3][6];
    __shared__ float sWr[16][68], sWi[16][68];    // [kk][node] (+pad)
    __shared__ float sVr[16][64], sVi[16][64];    // [kk][d]  (sVi negated)
    __shared__ int4  skint[KPAD];

    float invb[3] = { 1.0f / cell[b*9 + 0], 1.0f / cell[b*9 + 4], 1.0f / cell[b*9 + 8] };

    for (int fid = t; fid < 64 * 18; fid += 128) {
        int node = fid / 18; int rem = fid % 18; int a = rem / 6; int m = rem % 6;
        float u = pos[((size_t)(b*n + n0 + node)) * 3 + a] * invb[a];
        float tt = u * (float)m;
        tt -= floorf(tt);
        float sv, cv; sincospif(2.0f * tt, &sv, &cv);
        tabc[node][a][m] = cv;
        tabs[node][a][m] = sv;
    }
    for (int i = t; i < KPAD; i += 128) skint[i] = g_kint[b][i];

    unsigned long long acc2[4][4] = {};   // [n-pair][d j]
    __syncthreads();

    for (int k0c = 0; k0c < KPAD; k0c += 16) {
        #pragma unroll
        for (int r = 0; r < 8; r++) {
            int fid = t + r * 128;
            int kk = fid & 15, node = fid >> 4;
            float p = g_P[b][n0 + node][k0c + kk];
            float c, s;
            compose_e(&tabc[node][0][0], &tabs[node][0][0], skint[k0c + kk], c, s);
            sWr[kk][node] = p * c;
            sWi[kk][node] = p * s;
        }
        #pragma unroll
        for (int r = 0; r < 2; r++) {
            int fid = t + r * 128;
            int kk = fid >> 4, dq = fid & 15;
            float4 vr = *(const float4*)&g_vpot[0][b][k0c + kk][dq*4];
            float4 vi = *(const float4*)&g_vpot[1][b][k0c + kk][dq*4];
            *(float4*)&sVr[kk][dq*4] = vr;
            *(float4*)&sVi[kk][dq*4] = make_float4(-vi.x, -vi.y, -vi.z, -vi.w);
        }
        __syncthreads();
        #pragma unroll 4
        for (int kk = 0; kk < 16; kk++) {
            float4 wra = *(const float4*)&sWr[kk][tn*8];
            float4 wrb = *(const float4*)&sWr[kk][tn*8 + 4];
            float4 wia = *(const float4*)&sWi[kk][tn*8];
            float4 wib = *(const float4*)&sWi[kk][tn*8 + 4];
            float4 vr4 = *(const float4*)&sVr[kk][td*4];
            float4 vn4 = *(const float4*)&sVi[kk][td*4];
            unsigned long long wp[4] = { pk2(wra.x, wra.y), pk2(wra.z, wra.w),
                                         pk2(wrb.x, wrb.y), pk2(wrb.z, wrb.w) };
            unsigned long long ip[4] = { pk2(wia.x, wia.y), pk2(wia.z, wia.w),
                                         pk2(wib.x, wib.y), pk2(wib.z, wib.w) };
            float vr[4] = {vr4.x, vr4.y, vr4.z, vr4.w};
            float vn[4] = {vn4.x, vn4.y, vn4.z, vn4.w};
            #pragma unroll
            for (int j = 0; j < 4; j++) {
                unsigned long long bb = pk2(vr[j], vr[j]);
                unsigned long long cc = pk2(vn[j], vn[j]);
                #pragma unroll
                for (int p = 0; p < 4; p++) {
                    fma2(acc2[p][j], wp[p], bb);
                    fma2(acc2[p][j], ip[p], cc);
                }
            }
        }
        __syncthreads();
    }

    #pragma unroll
    for (int p = 0; p < 4; p++) {
        float2 a0 = up2(acc2[p][0]), a1 = up2(acc2[p][1]), a2 = up2(acc2[p][2]), a3 = up2(acc2[p][3]);
        float* opA = out + ((size_t)(b*n + n0 + tn*8 + p*2)) * 64 + td*4;
        float* opB = opA + 64;
        *(float4*)opA = make_float4(a0.x, a1.x, a2.x, a3.x);
        *(float4*)opB = make_float4(a0.y, a1.y, a2.y, a3.y);
    }
}

// ---------------- launch -----------------------------------------------------
// Order puts k_pot at launch #4 — the ncu window (observed: 4th launch) will
// finally profile the dominant kernel.
extern "C" void kernel_launch(void* const* d_in, const int* in_sizes, int n_in,
                              void* d_out, int out_size)
{
    const float* q    = (const float*)d_in[0];
    const float* kmat = (const float*)d_in[1];
    const float* vmat = (const float*)d_in[2];
    const float* pos  = (const float*)d_in[3];
    const float* cell = (const float*)d_in[4];
    // d_in[5] = batch indices (contiguous equal-size graphs; unused)

    int N = in_sizes[0] / 64;
    int B = in_sizes[4] / 9;
    int n = N / B;

    k_qT<<<dim3(n / 32, 1, B), dim3(32, 8)>>>(q, n, 0);    // 1
    k_qT<<<dim3(n / 32, 1, B), dim3(32, 8)>>>(q, n, 32);   // 2
    k_build<<<B, 32>>>(cell);                              // 3
    k_pot<<<dim3(KPAD / 64, NSPLIT, B), 256>>>(kmat, vmat, pos, cell, n);  // 4 (profiled)
    int total = 4 * B * KPAD * 64;
    k_reduce<<<(total + 255) / 256, 256>>>(B);             // 5
    k_z<<<dim3(KPAD / 64, n / 64, B), 128>>>(n);           // 6
    k_soft<<<dim3(n / 8, B), 256>>>(pos, cell, n);         // 7
    k_out<<<dim3(n / 64, B), 128>>>(pos, cell, (float*)d_out, n);  // 8
}